// round 1
// baseline (speedup 1.0000x reference)
#include <cuda_runtime.h>

// The 101-layer chain h <- relu(w*h + b) with w > 0 collapses exactly to
//   f(x) = S * max(x, C) + O
// because max(0, w*(S*max(x,C)+O) + b) = S'*max(x, max(C, -O'/S')) + O'
// with S' = w*S, O' = w*O + b.  A tiny single-thread kernel computes
// (S, C, O); the main kernel is a pure memory-bound elementwise stream.

__device__ float g_coef[3];  // S, C, O

__global__ void precompute_chain_kernel(const float* __restrict__ w,
                                        const float* __restrict__ b,
                                        int n_layers) {
    if (threadIdx.x == 0 && blockIdx.x == 0) {
        float S = 1.0f;
        float O = 0.0f;
        float C = -3.402823466e38f;  // -FLT_MAX
        for (int i = 0; i < n_layers; ++i) {
            float wi = w[i];
            float bi = b[i];
            S = wi * S;
            O = fmaf(wi, O, bi);
            // clamp threshold in x-space for this layer: S*x + O >= 0
            float t = -O / S;
            C = fmaxf(C, t);
        }
        g_coef[0] = S;
        g_coef[1] = C;
        g_coef[2] = O;
    }
}

__global__ void apply_chain_kernel(const float4* __restrict__ x4,
                                   float4* __restrict__ out4,
                                   const float* __restrict__ x,
                                   float* __restrict__ out,
                                   int n4, int n) {
    const float S = g_coef[0];
    const float C = g_coef[1];
    const float O = g_coef[2];

    int i = blockIdx.x * blockDim.x + threadIdx.x;
    if (i < n4) {
        float4 v = x4[i];
        float4 r;
        r.x = fmaf(S, fmaxf(v.x, C), O);
        r.y = fmaf(S, fmaxf(v.y, C), O);
        r.z = fmaf(S, fmaxf(v.z, C), O);
        r.w = fmaf(S, fmaxf(v.w, C), O);
        out4[i] = r;
    }
    // scalar tail (n not divisible by 4) — handled by one thread, negligible
    if (i == 0) {
        for (int j = n4 * 4; j < n; ++j) {
            out[j] = fmaf(S, fmaxf(x[j], C), O);
        }
    }
}

extern "C" void kernel_launch(void* const* d_in, const int* in_sizes, int n_in,
                              void* d_out, int out_size) {
    const float* x = (const float*)d_in[0];
    const float* w = (const float*)d_in[1];
    const float* b = (const float*)d_in[2];
    float* out = (float*)d_out;

    const int n        = in_sizes[0];
    const int n_layers = in_sizes[1];

    precompute_chain_kernel<<<1, 32>>>(w, b, n_layers);

    const int n4 = n / 4;
    const int threads = 256;
    const int blocks = (n4 + threads - 1) / threads;
    apply_chain_kernel<<<blocks, threads>>>(
        (const float4*)x, (float4*)out, x, out, n4, n);
}